// round 15
// baseline (speedup 1.0000x reference)
#include <cuda_runtime.h>
#include <cuda_fp16.h>
#include <math.h>
#include <stdint.h>

#define Bv 64
#define Tv 12
#define Nv 1024
#define Hv 64
#define Ev 16
#define Cv 65
#define O_G 128
#define O_U 64
#define KI 195
#define JG (KI*O_G)
#define JU (KI*O_U)
#define NB (Nv*Bv)
#define NCOLS (Bv*Cv)    // 4160

// ---------------- static device scratch ----------------
__device__ __align__(256) float g_eg[Tv*Nv*Ev];
__device__ __align__(256) float g_eu[Tv*Nv*Ev];
__device__ __align__(256) __half g_S[(size_t)2*Tv*Nv*Nv];      // fp16 sup
__device__ __align__(256) float g_biasg[Tv*Nv*O_G];
__device__ __align__(256) float g_biasu[Tv*Nv*O_U];
__device__ __align__(256) __half g_wg[(size_t)Nv*JG];          // fp16 weights
__device__ __align__(256) __half g_wu[(size_t)Nv*JU];
__device__ __align__(256) __half g_x0[(size_t)Nv*NCOLS];       // fp16 X planes
__device__ __align__(256) __half g_x1[(size_t)Nv*NCOLS];
__device__ __align__(256) __half g_x2[(size_t)Nv*NCOLS];
__device__ __align__(256) float g_h[NB*Hv];
__device__ __align__(256) float g_r[NB*Hv];

__device__ __forceinline__ float wredsum(float v) {
    #pragma unroll
    for (int o = 16; o; o >>= 1) v += __shfl_xor_sync(0xffffffffu, v, o);
    return v;
}
__device__ __forceinline__ float wredmax(float v) {
    #pragma unroll
    for (int o = 16; o; o >>= 1) v = fmaxf(v, __shfl_xor_sync(0xffffffffu, v, o));
    return v;
}
__device__ __forceinline__ unsigned f2tf(float x) {
    unsigned u; asm("cvt.rna.tf32.f32 %0, %1;" : "=r"(u) : "f"(x)); return u;
}
__device__ __forceinline__ void cp16(uint32_t dst, const void* src, int sz) {
    asm volatile("cp.async.cg.shared.global [%0], [%1], 16, %2;"
                 :: "r"(dst), "l"((unsigned long long)__cvta_generic_to_global(src)), "r"(sz));
}
__device__ __forceinline__ void cpcommit() { asm volatile("cp.async.commit_group;"); }
__device__ __forceinline__ uint32_t s2u(const void* p) {
    return (uint32_t)__cvta_generic_to_shared(p);
}
__device__ __forceinline__ void mma8(float* acc, const uint32_t* a, const uint32_t* b) {
    asm volatile(
        "mma.sync.aligned.m16n8k8.row.col.f32.tf32.tf32.f32 "
        "{%0,%1,%2,%3}, {%4,%5,%6,%7}, {%8,%9}, {%0,%1,%2,%3};"
        : "+f"(acc[0]), "+f"(acc[1]), "+f"(acc[2]), "+f"(acc[3])
        : "r"(a[0]), "r"(a[1]), "r"(a[2]), "r"(a[3]), "r"(b[0]), "r"(b[1]));
}
__device__ __forceinline__ void mmaH(float* c, const uint32_t* a, uint32_t b0, uint32_t b1) {
    asm volatile(
        "mma.sync.aligned.m16n8k16.row.col.f32.f16.f16.f32 "
        "{%0,%1,%2,%3}, {%4,%5,%6,%7}, {%8,%9}, {%0,%1,%2,%3};"
        : "+f"(c[0]), "+f"(c[1]), "+f"(c[2]), "+f"(c[3])
        : "r"(a[0]), "r"(a[1]), "r"(a[2]), "r"(a[3]), "r"(b0), "r"(b1));
}
__device__ __forceinline__ void ldsm4(uint32_t* r, uint32_t addr) {
    asm volatile("ldmatrix.sync.aligned.m8n8.x4.shared.b16 {%0,%1,%2,%3}, [%4];"
        : "=r"(r[0]), "=r"(r[1]), "=r"(r[2]), "=r"(r[3]) : "r"(addr));
}
__device__ __forceinline__ void ldsm4t(uint32_t* r, uint32_t addr) {
    asm volatile("ldmatrix.sync.aligned.m8n8.x4.trans.shared.b16 {%0,%1,%2,%3}, [%4];"
        : "=r"(r[0]), "=r"(r[1]), "=r"(r[2]), "=r"(r[3]) : "r"(addr));
}

// ---------------- embed ----------------
__global__ void k_embed(const float* __restrict__ node_emb, const float* __restrict__ time_emb,
                        const float* __restrict__ glng, const float* __restrict__ glnb,
                        const float* __restrict__ ulng, const float* __restrict__ ulnb) {
    int idx = blockIdx.x * blockDim.x + threadIdx.x;
    if (idx >= Tv * Nv) return;
    int t = idx / Nv, n = idx - t * Nv;
    float x[Ev]; float m = 0.f;
    #pragma unroll
    for (int d = 0; d < Ev; d++) { x[d] = node_emb[n*Ev+d] + time_emb[t*Ev+d]; m += x[d]; }
    m *= (1.0f / Ev);
    float v = 0.f;
    #pragma unroll
    for (int d = 0; d < Ev; d++) { float dd = x[d] - m; v += dd * dd; }
    v *= (1.0f / Ev);
    float inv = rsqrtf(v + 1e-12f);
    #pragma unroll
    for (int d = 0; d < Ev; d++) {
        float eh = (x[d] - m) * inv;
        g_eg[(size_t)idx*Ev + d] = eh * glng[d] + glnb[d];
        g_eu[(size_t)idx*Ev + d] = eh * ulng[d] + ulnb[d];
    }
}

// ---------------- sup = softmax(e e^T), fp16 ----------------
__global__ __launch_bounds__(256) void k_sup() {
    extern __shared__ float se[];
    int bt = blockIdx.y; int t = bt >> 1; int br = bt & 1;
    const float* e = (br ? g_eu : g_eg) + (size_t)t * Nv * Ev;
    __half* S = g_S + ((size_t)(br*Tv + t) << 20);
    for (int i = threadIdx.x; i < Nv * Ev; i += 256) se[(i >> 4)*17 + (i & 15)] = e[i];
    __syncthreads();
    int wid = threadIdx.x >> 5, lane = threadIdx.x & 31;
    #pragma unroll
    for (int rr = 0; rr < 2; rr++) {
        int n = blockIdx.x * 16 + wid * 2 + rr;
        float er[Ev];
        #pragma unroll
        for (int d = 0; d < Ev; d++) er[d] = se[n*17 + d];
        float lg[32]; float mx = -1e30f;
        #pragma unroll
        for (int ii = 0; ii < 32; ii++) {
            const float* em = &se[(ii*32 + lane)*17];
            float s = 0.f;
            #pragma unroll
            for (int d = 0; d < Ev; d++) s = fmaf(er[d], em[d], s);
            lg[ii] = s; mx = fmaxf(mx, s);
        }
        mx = wredmax(mx);
        float sum = 0.f;
        #pragma unroll
        for (int ii = 0; ii < 32; ii++) { lg[ii] = expf(lg[ii] - mx); sum += lg[ii]; }
        sum = wredsum(sum);
        float inv = 1.0f / sum;
        #pragma unroll
        for (int ii = 0; ii < 32; ii++)
            S[(size_t)n * Nv + ii*32 + lane] = __float2half(lg[ii] * inv);
    }
}

// ---------------- bias ----------------
__global__ void k_bias(const float* __restrict__ bp, int O, int branch) {
    int idx = blockIdx.x * blockDim.x + threadIdx.x;
    if (idx >= Tv * Nv * O) return;
    int o = idx % O; int tn = idx / O;
    const float* e = (branch ? g_eu : g_eg) + (size_t)tn * Ev;
    float* out = branch ? g_biasu : g_biasg;
    float s = 0.f;
    #pragma unroll
    for (int d = 0; d < Ev; d++) s = fmaf(e[d], bp[d*O + o], s);
    out[idx] = s;
}

// ---------------- wgen -> fp16 ----------------
__global__ __launch_bounds__(256) void k_wgen(const float* __restrict__ wp, int t, int J, int branch) {
    __shared__ float swp[Ev][256];
    __shared__ float sen[32][Ev];
    const float* e = (branch ? g_eu : g_eg) + (size_t)t * Nv * Ev;
    __half* w = branch ? g_wu : g_wg;
    int j = blockIdx.x * 256 + threadIdx.x;
    int n0 = blockIdx.y * 32;
    for (int i = threadIdx.x; i < 32 * Ev; i += 256)
        sen[i >> 4][i & 15] = e[(size_t)(n0 + (i >> 4))*Ev + (i & 15)];
    #pragma unroll
    for (int s = 0; s < Ev; s++)
        swp[s][threadIdx.x] = (j < J) ? wp[(size_t)s*J + j] : 0.f;
    __syncthreads();
    if (j >= J) return;
    for (int nn = 0; nn < 32; nn++) {
        float s = 0.f;
        #pragma unroll
        for (int d = 0; d < Ev; d++) s = fmaf(sen[nn][d], swp[d][threadIdx.x], s);
        w[(size_t)(n0 + nn)*J + j] = __float2half(s);
    }
}

// ---------------- X0 init ----------------
__global__ void k_buildX0(const float* __restrict__ src) {
    int idx = blockIdx.x * blockDim.x + threadIdx.x;
    if (idx >= Nv * NCOLS) return;
    int col = idx % NCOLS; int n = idx / NCOLS;
    int c = col % Cv;
    float v = 0.f;
    if (c == 0) { int b = col / Cv; v = src[(size_t)(b*Tv)*Nv + n]; }
    g_x0[idx] = __float2half(v);
}

// ---------------- fp16 GEMM: CTA 128x256, 512 thr (16 warps, 4Mx4N), K-tile 32 ----------------
#define ASTR 80                    // bytes/A row (32 halves + pad)
#define BSTR 528                   // bytes/B row (256 halves + pad)
#define BOFF 10240                 // 128*80
#define STGB (BOFF + 32*BSTR)      // 27136
__global__ __launch_bounds__(512) void k_hgemm(int branch, int t, int stage) {
    extern __shared__ uint8_t smem[];
    const __half* A = g_S + ((size_t)(branch*Tv + t) << 20);
    const __half* Bm = (stage == 1) ? g_x0 : g_x1;

    int tid = threadIdx.x, lane = tid & 31, wid = tid >> 5;
    int wm = wid & 3, wn = wid >> 2;                 // 4M x 4N warps, warp tile 32x64
    int row0 = blockIdx.y * 128, col0 = blockIdx.x * 256;
    int g = lane >> 2, tg = lane & 3;
    int quad = lane >> 3, qr = lane & 7;
    uint32_t sb = s2u(smem);

    auto issue = [&](int kt, int s) {
        uint32_t base = sb + (uint32_t)s * STGB;
        {                                               // A: 512 x 16B (1/thread)
            int row = tid >> 2, kc = tid & 3;
            cp16(base + (uint32_t)(row * ASTR + kc * 16),
                 A + (size_t)(row0 + row) * Nv + kt + kc * 8, 16);
        }
        #pragma unroll
        for (int q = 0; q < 2; q++) {                   // B: 1024 x 16B (2/thread)
            int id = tid + q * 512;
            int row = id >> 5, cc = id & 31;
            int gc = col0 + cc * 8;
            int sz = (gc < NCOLS) ? 16 : 0;
            cp16(base + BOFF + (uint32_t)(row * BSTR + cc * 16),
                 Bm + (size_t)(kt + row) * NCOLS + (sz ? gc : 0), sz);
        }
        cpcommit();
    };

    float acc[2][8][4];
    #pragma unroll
    for (int mi = 0; mi < 2; mi++)
        #pragma unroll
        for (int n8 = 0; n8 < 8; n8++)
            #pragma unroll
            for (int q = 0; q < 4; q++) acc[mi][n8][q] = 0.f;

    issue(0, 0); issue(32, 1); issue(64, 2);

    for (int it = 0; it < 32; it++) {
        asm volatile("cp.async.wait_group 2;");
        __syncthreads();
        if (it + 3 < 32) issue((it + 3) * 32, (it + 3) & 3);
        else cpcommit();
        uint32_t base = sb + (uint32_t)(it & 3) * STGB;

        #pragma unroll
        for (int ks = 0; ks < 2; ks++) {
            int k0 = ks * 16;
            uint32_t af[2][4], bf[4][4];
            #pragma unroll
            for (int mi = 0; mi < 2; mi++) {
                int trow = wm * 32 + mi * 16 + (quad & 1) * 8 + qr;
                ldsm4(af[mi], base + (uint32_t)(trow * ASTR + (k0 + (quad >> 1) * 8) * 2));
            }
            #pragma unroll
            for (int nj = 0; nj < 4; nj++) {
                int ncol = wn * 64 + nj * 16 + (quad >> 1) * 8;
                ldsm4t(bf[nj], base + BOFF +
                       (uint32_t)((k0 + (quad & 1) * 8 + qr) * BSTR + ncol * 2));
            }
            #pragma unroll
            for (int mi = 0; mi < 2; mi++)
                #pragma unroll
                for (int n8 = 0; n8 < 8; n8++)
                    mmaH(acc[mi][n8], af[mi], bf[n8 >> 1][(n8 & 1) * 2], bf[n8 >> 1][(n8 & 1) * 2 + 1]);
        }
    }

    #pragma unroll
    for (int mi = 0; mi < 2; mi++) {
        int r = row0 + wm * 32 + mi * 16 + g;
        #pragma unroll
        for (int n8 = 0; n8 < 8; n8++) {
            int c = col0 + wn * 64 + n8 * 8 + tg * 2;
            if (c < NCOLS) {
                if (stage == 1) {
                    *(__half2*)(g_x1 + (size_t)r * NCOLS + c) =
                        __floats2half2_rn(acc[mi][n8][0], acc[mi][n8][1]);
                    *(__half2*)(g_x1 + (size_t)(r + 8) * NCOLS + c) =
                        __floats2half2_rn(acc[mi][n8][2], acc[mi][n8][3]);
                } else {
                    float2 d0 = __half22float2(*(const __half2*)(g_x0 + (size_t)r * NCOLS + c));
                    float2 d1 = __half22float2(*(const __half2*)(g_x0 + (size_t)(r + 8) * NCOLS + c));
                    *(__half2*)(g_x2 + (size_t)r * NCOLS + c) =
                        __floats2half2_rn(2.f * acc[mi][n8][0] - d0.x, 2.f * acc[mi][n8][1] - d0.y);
                    *(__half2*)(g_x2 + (size_t)(r + 8) * NCOLS + c) =
                        __floats2half2_rn(2.f * acc[mi][n8][2] - d1.x, 2.f * acc[mi][n8][3] - d1.y);
                }
            }
        }
    }
}

// ---------------- XG read (fp16 -> tf32 bits, exact) ----------------
__device__ __forceinline__ uint32_t xg_tf32(int k, int n, int col) {
    size_t p = (size_t)n * NCOLS + col;
    __half v = (k == 0) ? g_x0[p] : (k == 1) ? g_x1[p] : g_x2[p];
    return f2tf(__half2float(v));
}
__device__ __forceinline__ uint32_t h2tf(__half h) { return f2tf(__half2float(h)); }

// ---------------- node gate GEMM (tf32 mma, fp16 W stream) ----------------
#define NG_SMEM (64*204*4 + 3*8*136*2)
__global__ __launch_bounds__(256) void k_nodegate(int t) {
    extern __shared__ uint32_t sm[];
    uint32_t* sA = sm;                        // [64][204] tf32
    __half*   sW = (__half*)(sm + 64 * 204);  // [3][8][136] fp16
    int n = blockIdx.x;
    int tid = threadIdx.x, lane = tid & 31, wid = tid >> 5;
    int wm = wid & 3, wn = wid >> 2;
    int g = lane >> 2, tg = lane & 3;

    for (int idx = tid; idx < 64 * 195; idx += 256) {
        int b = idx / 195, ki = idx - b * 195;
        int k = ki / Cv, c = ki - k * Cv;
        sA[b * 204 + ki] = xg_tf32(k, n, b * Cv + c);
    }
    for (int idx = tid; idx < 64 * 9; idx += 256)
        sA[(idx / 9) * 204 + 195 + (idx % 9)] = 0;
    uint32_t wbase = s2u(sW);
    const __half* Wg = g_wg + (size_t)n * JG;
    int wr = tid >> 5, ci = tid & 31;         // 16 valid cols of 8 halves
    auto issueW = [&](int kc, int s) {
        if (ci < 16) {
            int ki = kc * 8 + wr;
            int sz = (ki < KI) ? 16 : 0;
            cp16(wbase + (uint32_t)((s * 8 + wr) * 136 + ci * 8) * 2u,
                 Wg + (size_t)(ki < KI ? ki : 0) * O_G + ci * 8, sz);
        }
        cpcommit();
    };
    float acc[8][4];
    #pragma unroll
    for (int j = 0; j < 8; j++) { acc[j][0]=acc[j][1]=acc[j][2]=acc[j][3]=0.f; }
    issueW(0, 0); issueW(1, 1);
    for (int kc = 0; kc < 25; kc++) {
        asm volatile("cp.async.wait_group 1;");
        __syncthreads();
        if (kc + 2 < 25) issueW(kc + 2, (kc + 2) % 3); else cpcommit();
        const __half* Ws_ = sW + (kc % 3) * 8 * 136;
        int r = wm * 16 + g;
        int kcol = kc * 8;
        uint32_t af[4];
        af[0] = sA[r * 204 + kcol + tg];
        af[1] = sA[(r + 8) * 204 + kcol + tg];
        af[2] = sA[r * 204 + kcol + tg + 4];
        af[3] = sA[(r + 8) * 204 + kcol + tg + 4];
        #pragma unroll
        for (int j = 0; j < 8; j++) {
            uint32_t bf[2];
            int nn = wn * 64 + j * 8 + g;
            bf[0] = h2tf(Ws_[tg * 136 + nn]);
            bf[1] = h2tf(Ws_[(tg + 4) * 136 + nn]);
            mma8(acc[j], af, bf);
        }
    }
    const float* bias = g_biasg + ((size_t)t * Nv + n) * O_G;
    int b1 = wm * 16 + g;
    #pragma unroll
    for (int j = 0; j < 8; j++) {
        int o0 = wn * 64 + j * 8 + tg * 2;
        #pragma unroll
        for (int h = 0; h < 2; h++) {
            int b = b1 + h * 8;
            size_t base = ((size_t)n * Bv + b) * Hv;
            #pragma unroll
            for (int q = 0; q < 2; q++) {
                int oo = o0 + q;
                float s = 1.0f / (1.0f + expf(-(acc[j][h*2+q] + bias[oo])));
                if (oo < Hv) {
                    g_x0[(size_t)n * NCOLS + b * Cv + 1 + oo] = __float2half(s * g_h[base + oo]);
                } else g_r[base + oo - Hv] = s;
            }
        }
    }
}

// ---------------- node update GEMM ----------------
#define NU_SMEM (64*204*4 + 3*8*72*2)
__global__ __launch_bounds__(256) void k_nodeupd(const float* __restrict__ src, int t) {
    extern __shared__ uint32_t sm[];
    uint32_t* sA = sm;
    __half*   sW = (__half*)(sm + 64 * 204);
    int n = blockIdx.x;
    int tid = threadIdx.x, lane = tid & 31, wid = tid >> 5;
    int wm = wid & 3, wn = wid >> 2;
    int g = lane >> 2, tg = lane & 3;

    for (int idx = tid; idx < 64 * 195; idx += 256) {
        int b = idx / 195, ki = idx - b * 195;
        int k = ki / Cv, c = ki - k * Cv;
        sA[b * 204 + ki] = xg_tf32(k, n, b * Cv + c);
    }
    for (int idx = tid; idx < 64 * 9; idx += 256)
        sA[(idx / 9) * 204 + 195 + (idx % 9)] = 0;
    uint32_t wbase = s2u(sW);
    const __half* Wu = g_wu + (size_t)n * JU;
    int wr = tid >> 5, ci = tid & 31;         // 8 valid cols of 8 halves
    auto issueW = [&](int kc, int s) {
        if (ci < 8) {
            int ki = kc * 8 + wr;
            int sz = (ki < KI) ? 16 : 0;
            cp16(wbase + (uint32_t)((s * 8 + wr) * 72 + ci * 8) * 2u,
                 Wu + (size_t)(ki < KI ? ki : 0) * O_U + ci * 8, sz);
        }
        cpcommit();
    };
    float acc[4][4];
    #pragma unroll
    for (int j = 0; j < 4; j++) { acc[j][0]=acc[j][1]=acc[j][2]=acc[j][3]=0.f; }
    issueW(0, 0); issueW(1, 1);
    for (int kc = 0; kc < 25; kc++) {
        asm volatile("cp.async.wait_group 1;");
        __syncthreads();
        if (kc + 2 < 25) issueW(kc + 2, (kc + 2) % 3); else cpcommit();
        const __half* Ws_ = sW + (kc % 3) * 8 * 72;
        int r = wm * 16 + g;
        int kcol = kc * 8;
        uint32_t af[4];
        af[0] = sA[r * 204 + kcol + tg];
        af[1] = sA[(r + 8) * 204 + kcol + tg];
        af[2] = sA[r * 204 + kcol + tg + 4];
        af[3] = sA[(r + 8) * 204 + kcol + tg + 4];
        #pragma unroll
        for (int j = 0; j < 4; j++) {
            uint32_t bf[2];
            int nn = wn * 32 + j * 8 + g;
            bf[0] = h2tf(Ws_[tg * 72 + nn]);
            bf[1] = h2tf(Ws_[(tg + 4) * 72 + nn]);
            mma8(acc[j], af, bf);
        }
    }
    const float* bias = g_biasu + ((size_t)t * Nv + n) * O_U;
    int b1 = wm * 16 + g;
    #pragma unroll
    for (int j = 0; j < 4; j++) {
        int o0 = wn * 32 + j * 8 + tg * 2;
        #pragma unroll
        for (int h = 0; h < 2; h++) {
            int b = b1 + h * 8;
            size_t base = ((size_t)n * Bv + b) * Hv;
            #pragma unroll
            for (int q = 0; q < 2; q++) {
                int oo = o0 + q;
                float hc = tanhf(acc[j][h*2+q] + bias[oo]);
                float rr = g_r[base + oo];
                float hnew = rr * g_h[base + oo] + (1.0f - rr) * hc;
                g_h[base + oo] = hnew;
                size_t p = (size_t)n * NCOLS + b * Cv + 1 + oo;
                g_x0[p] = __float2half(hnew);
                if (oo == 0 && t + 1 < Tv)
                    g_x0[p - 1] = __float2half(src[(size_t)(b * Tv + t + 1) * Nv + n]);
            }
        }
    }
}

__global__ void k_zeroh() {
    int idx = blockIdx.x * blockDim.x + threadIdx.x;
    if (idx < NB * Hv) g_h[idx] = 0.f;
}

__global__ void k_final(const float* __restrict__ out_lng, const float* __restrict__ out_lnb,
                        const float* __restrict__ conv_w, const float* __restrict__ conv_b,
                        float* __restrict__ out) {
    int gw = (blockIdx.x * blockDim.x + threadIdx.x) >> 5;
    int lane = threadIdx.x & 31;
    if (gw >= NB) return;
    int n = gw / Bv, b = gw - n * Bv;
    const float* hp = g_h + (size_t)gw * Hv;
    float x0 = hp[lane], x1 = hp[lane + 32];
    float m = wredsum(x0 + x1) * (1.0f / Hv);
    float d0 = x0 - m, d1 = x1 - m;
    float vs = wredsum(d0 * d0 + d1 * d1) * (1.0f / Hv);
    float inv = rsqrtf(vs + 1e-12f);
    float y0 = d0 * inv * out_lng[lane]      + out_lnb[lane];
    float y1 = d1 * inv * out_lng[lane + 32] + out_lnb[lane + 32];
    #pragma unroll
    for (int o = 0; o < Tv; o++) {
        float p = y0 * conv_w[o*Hv + lane] + y1 * conv_w[o*Hv + lane + 32];
        p = wredsum(p);
        if (lane == 0) out[(size_t)(b*Tv + o)*Nv + n] = p + conv_b[o];
    }
}

// ================================================================================
extern "C" void kernel_launch(void* const* d_in, const int* in_sizes, int n_in,
                              void* d_out, int out_size) {
    const float* source   = (const float*)d_in[0];
    const float* node_emb = (const float*)d_in[1];
    const float* time_emb = (const float*)d_in[2];
    const float* gate_wp  = (const float*)d_in[3];
    const float* gate_bp  = (const float*)d_in[4];
    const float* gate_lng = (const float*)d_in[5];
    const float* gate_lnb = (const float*)d_in[6];
    const float* upd_wp   = (const float*)d_in[7];
    const float* upd_bp   = (const float*)d_in[8];
    const float* upd_lng  = (const float*)d_in[9];
    const float* upd_lnb  = (const float*)d_in[10];
    const float* out_lng  = (const float*)d_in[11];
    const float* out_lnb  = (const float*)d_in[12];
    const float* conv_w   = (const float*)d_in[13];
    const float* conv_b   = (const float*)d_in[14];
    float* out = (float*)d_out;

    cudaFuncSetAttribute(k_sup,      cudaFuncAttributeMaxDynamicSharedMemorySize, 1024*17*4);
    cudaFuncSetAttribute(k_hgemm,    cudaFuncAttributeMaxDynamicSharedMemorySize, 4*STGB);
    cudaFuncSetAttribute(k_nodegate, cudaFuncAttributeMaxDynamicSharedMemorySize, NG_SMEM);
    cudaFuncSetAttribute(k_nodeupd,  cudaFuncAttributeMaxDynamicSharedMemorySize, NU_SMEM);

    dim3 hGrid((NCOLS + 255)/256, Nv/128);   // 17 x 8 = 136 CTAs = 1 wave

    // launch index 3 = k_hgemm (the slot ncu samples)
    k_embed<<<(Tv*Nv + 255)/256, 256>>>(node_emb, time_emb, gate_lng, gate_lnb, upd_lng, upd_lnb);
    k_sup<<<dim3(Nv/16, Tv*2), 256, 1024*17*4>>>();
    k_buildX0<<<(Nv*NCOLS + 255)/256, 256>>>(source);
    k_hgemm<<<hGrid, 512, 4*STGB>>>(0, 0, 1);          // launch idx 3
    k_hgemm<<<hGrid, 512, 4*STGB>>>(0, 0, 2);
    k_wgen<<<dim3((JG + 255)/256, Nv/32), 256>>>(gate_wp, 0, JG, 0);
    k_zeroh<<<(NB*Hv + 255)/256, 256>>>();
    k_bias<<<(Tv*Nv*O_G + 255)/256, 256>>>(gate_bp, O_G, 0);
    k_bias<<<(Tv*Nv*O_U + 255)/256, 256>>>(upd_bp,  O_U, 1);
    k_nodegate<<<Nv, 256, NG_SMEM>>>(0);
    k_wgen<<<dim3((JU + 255)/256, Nv/32), 256>>>(upd_wp, 0, JU, 1);
    k_hgemm<<<hGrid, 512, 4*STGB>>>(1, 0, 1);
    k_hgemm<<<hGrid, 512, 4*STGB>>>(1, 0, 2);
    k_nodeupd<<<Nv, 256, NU_SMEM>>>(source, 0);

    for (int t = 1; t < Tv; t++) {
        k_wgen<<<dim3((JG + 255)/256, Nv/32), 256>>>(gate_wp, t, JG, 0);
        k_hgemm<<<hGrid, 512, 4*STGB>>>(0, t, 1);
        k_hgemm<<<hGrid, 512, 4*STGB>>>(0, t, 2);
        k_nodegate<<<Nv, 256, NG_SMEM>>>(t);
        k_wgen<<<dim3((JU + 255)/256, Nv/32), 256>>>(upd_wp, t, JU, 1);
        k_hgemm<<<hGrid, 512, 4*STGB>>>(1, t, 1);
        k_hgemm<<<hGrid, 512, 4*STGB>>>(1, t, 2);
        k_nodeupd<<<Nv, 256, NU_SMEM>>>(source, t);
    }

    k_final<<<(NB*32 + 255)/256, 256>>>(out_lng, out_lnb, conv_w, conv_b, out);
}

// round 16
// speedup vs baseline: 1.3260x; 1.3260x over previous
#include <cuda_runtime.h>
#include <cuda_fp16.h>
#include <math.h>
#include <stdint.h>

#define Bv 64
#define Tv 12
#define Nv 1024
#define Hv 64
#define Ev 16
#define Cv 65
#define O_G 128
#define O_U 64
#define KI 195
#define JG (KI*O_G)
#define JU (KI*O_U)
#define NB (Nv*Bv)
#define NCOLS (Bv*Cv)    // 4160; column layout: col = c*64 + b

// ---------------- static device scratch ----------------
__device__ __align__(256) float g_eg[Tv*Nv*Ev];
__device__ __align__(256) float g_eu[Tv*Nv*Ev];
__device__ __align__(256) __half g_S[(size_t)2*Tv*Nv*Nv];      // fp16 sup
__device__ __align__(256) float g_biasg[Tv*Nv*O_G];
__device__ __align__(256) float g_biasu[Tv*Nv*O_U];
__device__ __align__(256) __half g_wg[(size_t)Nv*JG];          // fp16 weights
__device__ __align__(256) __half g_wu[(size_t)Nv*JU];
__device__ __align__(256) __half g_x0[(size_t)Nv*NCOLS];       // fp16 X planes (col = c*64+b)
__device__ __align__(256) __half g_x1[(size_t)Nv*NCOLS];
__device__ __align__(256) __half g_x2[(size_t)Nv*NCOLS];
__device__ __align__(256) float g_h[NB*Hv];
__device__ __align__(256) float g_r[NB*Hv];

__device__ __forceinline__ float wredsum(float v) {
    #pragma unroll
    for (int o = 16; o; o >>= 1) v += __shfl_xor_sync(0xffffffffu, v, o);
    return v;
}
__device__ __forceinline__ float wredmax(float v) {
    #pragma unroll
    for (int o = 16; o; o >>= 1) v = fmaxf(v, __shfl_xor_sync(0xffffffffu, v, o));
    return v;
}
__device__ __forceinline__ void cp16(uint32_t dst, const void* src, int sz) {
    asm volatile("cp.async.cg.shared.global [%0], [%1], 16, %2;"
                 :: "r"(dst), "l"((unsigned long long)__cvta_generic_to_global(src)), "r"(sz));
}
__device__ __forceinline__ void cpcommit() { asm volatile("cp.async.commit_group;"); }
__device__ __forceinline__ uint32_t s2u(const void* p) {
    return (uint32_t)__cvta_generic_to_shared(p);
}
__device__ __forceinline__ void mmaH(float* c, const uint32_t* a, uint32_t b0, uint32_t b1) {
    asm volatile(
        "mma.sync.aligned.m16n8k16.row.col.f32.f16.f16.f32 "
        "{%0,%1,%2,%3}, {%4,%5,%6,%7}, {%8,%9}, {%0,%1,%2,%3};"
        : "+f"(c[0]), "+f"(c[1]), "+f"(c[2]), "+f"(c[3])
        : "r"(a[0]), "r"(a[1]), "r"(a[2]), "r"(a[3]), "r"(b0), "r"(b1));
}
__device__ __forceinline__ void ldsm4(uint32_t* r, uint32_t addr) {
    asm volatile("ldmatrix.sync.aligned.m8n8.x4.shared.b16 {%0,%1,%2,%3}, [%4];"
        : "=r"(r[0]), "=r"(r[1]), "=r"(r[2]), "=r"(r[3]) : "r"(addr));
}
__device__ __forceinline__ void ldsm4t(uint32_t* r, uint32_t addr) {
    asm volatile("ldmatrix.sync.aligned.m8n8.x4.trans.shared.b16 {%0,%1,%2,%3}, [%4];"
        : "=r"(r[0]), "=r"(r[1]), "=r"(r[2]), "=r"(r[3]) : "r"(addr));
}

// ---------------- embed ----------------
__global__ void k_embed(const float* __restrict__ node_emb, const float* __restrict__ time_emb,
                        const float* __restrict__ glng, const float* __restrict__ glnb,
                        const float* __restrict__ ulng, const float* __restrict__ ulnb) {
    int idx = blockIdx.x * blockDim.x + threadIdx.x;
    if (idx >= Tv * Nv) return;
    int t = idx / Nv, n = idx - t * Nv;
    float x[Ev]; float m = 0.f;
    #pragma unroll
    for (int d = 0; d < Ev; d++) { x[d] = node_emb[n*Ev+d] + time_emb[t*Ev+d]; m += x[d]; }
    m *= (1.0f / Ev);
    float v = 0.f;
    #pragma unroll
    for (int d = 0; d < Ev; d++) { float dd = x[d] - m; v += dd * dd; }
    v *= (1.0f / Ev);
    float inv = rsqrtf(v + 1e-12f);
    #pragma unroll
    for (int d = 0; d < Ev; d++) {
        float eh = (x[d] - m) * inv;
        g_eg[(size_t)idx*Ev + d] = eh * glng[d] + glnb[d];
        g_eu[(size_t)idx*Ev + d] = eh * ulng[d] + ulnb[d];
    }
}

// ---------------- sup = softmax(e e^T), fp16 ----------------
__global__ __launch_bounds__(256) void k_sup() {
    extern __shared__ float se[];
    int bt = blockIdx.y; int t = bt >> 1; int br = bt & 1;
    const float* e = (br ? g_eu : g_eg) + (size_t)t * Nv * Ev;
    __half* S = g_S + ((size_t)(br*Tv + t) << 20);
    for (int i = threadIdx.x; i < Nv * Ev; i += 256) se[(i >> 4)*17 + (i & 15)] = e[i];
    __syncthreads();
    int wid = threadIdx.x >> 5, lane = threadIdx.x & 31;
    #pragma unroll
    for (int rr = 0; rr < 2; rr++) {
        int n = blockIdx.x * 16 + wid * 2 + rr;
        float er[Ev];
        #pragma unroll
        for (int d = 0; d < Ev; d++) er[d] = se[n*17 + d];
        float lg[32]; float mx = -1e30f;
        #pragma unroll
        for (int ii = 0; ii < 32; ii++) {
            const float* em = &se[(ii*32 + lane)*17];
            float s = 0.f;
            #pragma unroll
            for (int d = 0; d < Ev; d++) s = fmaf(er[d], em[d], s);
            lg[ii] = s; mx = fmaxf(mx, s);
        }
        mx = wredmax(mx);
        float sum = 0.f;
        #pragma unroll
        for (int ii = 0; ii < 32; ii++) { lg[ii] = expf(lg[ii] - mx); sum += lg[ii]; }
        sum = wredsum(sum);
        float inv = 1.0f / sum;
        #pragma unroll
        for (int ii = 0; ii < 32; ii++)
            S[(size_t)n * Nv + ii*32 + lane] = __float2half(lg[ii] * inv);
    }
}

// ---------------- bias ----------------
__global__ void k_bias(const float* __restrict__ bp, int O, int branch) {
    int idx = blockIdx.x * blockDim.x + threadIdx.x;
    if (idx >= Tv * Nv * O) return;
    int o = idx % O; int tn = idx / O;
    const float* e = (branch ? g_eu : g_eg) + (size_t)tn * Ev;
    float* out = branch ? g_biasu : g_biasg;
    float s = 0.f;
    #pragma unroll
    for (int d = 0; d < Ev; d++) s = fmaf(e[d], bp[d*O + o], s);
    out[idx] = s;
}

// ---------------- wgen -> fp16, wp read once per block, 128 nodes/block ----------------
__global__ __launch_bounds__(256) void k_wgen(const float* __restrict__ wp, int t, int J, int branch) {
    __shared__ float swp[Ev][256];
    __shared__ float sen[32][Ev + 1];
    const float* e = (branch ? g_eu : g_eg) + (size_t)t * Nv * Ev;
    __half* w = branch ? g_wu : g_wg;
    int tid = threadIdx.x;
    int j = blockIdx.x * 256 + tid;
    #pragma unroll
    for (int s = 0; s < Ev; s++)
        swp[s][tid] = (j < J) ? wp[(size_t)s*J + j] : 0.f;
    int nbase = blockIdx.y * 128;
    for (int cchunk = 0; cchunk < 4; cchunk++) {
        int n0 = nbase + cchunk * 32;
        __syncthreads();
        for (int i = tid; i < 32 * Ev; i += 256)
            sen[i >> 4][i & 15] = e[(size_t)(n0 + (i >> 4))*Ev + (i & 15)];
        __syncthreads();
        if (j < J) {
            for (int nn = 0; nn < 32; nn++) {
                float s = 0.f;
                #pragma unroll
                for (int d = 0; d < Ev; d++) s = fmaf(sen[nn][d], swp[d][tid], s);
                w[(size_t)(n0 + nn)*J + j] = __float2half(s);
            }
        }
    }
}

// ---------------- X0 init (col = c*64 + b) ----------------
__global__ void k_buildX0(const float* __restrict__ src) {
    int idx = blockIdx.x * blockDim.x + threadIdx.x;
    if (idx >= Nv * NCOLS) return;
    int col = idx % NCOLS; int n = idx / NCOLS;
    int cc = col >> 6, b = col & 63;
    float v = 0.f;
    if (cc == 0) v = src[(size_t)(b*Tv)*Nv + n];
    g_x0[idx] = __float2half(v);
}

// ---------------- fp16 GEMM (R13 best): CTA 128x256, 256 thr, K-tile 32, 4-stage ----------------
#define ASTR 80
#define BSTR 528
#define BOFF 10240
#define STGB (BOFF + 32*BSTR)      // 27136
__global__ __launch_bounds__(256) void k_hgemm(int branch, int t, int stage) {
    extern __shared__ uint8_t smem[];
    const __half* A = g_S + ((size_t)(branch*Tv + t) << 20);
    const __half* Bm = (stage == 1) ? g_x0 : g_x1;

    int tid = threadIdx.x, lane = tid & 31, wid = tid >> 5;
    int wm = wid & 1, wn = wid >> 1;
    int row0 = blockIdx.y * 128, col0 = blockIdx.x * 256;
    int g = lane >> 2, tg = lane & 3;
    int quad = lane >> 3, qr = lane & 7;
    uint32_t sb = s2u(smem);

    auto issue = [&](int kt, int s) {
        uint32_t base = sb + (uint32_t)s * STGB;
        #pragma unroll
        for (int q = 0; q < 2; q++) {
            int id = tid + q * 256;
            int row = id >> 2, kc = id & 3;
            cp16(base + (uint32_t)(row * ASTR + kc * 16),
                 A + (size_t)(row0 + row) * Nv + kt + kc * 8, 16);
        }
        #pragma unroll
        for (int q = 0; q < 4; q++) {
            int id = tid + q * 256;
            int row = id >> 5, cc = id & 31;
            int gc = col0 + cc * 8;
            int sz = (gc < NCOLS) ? 16 : 0;
            cp16(base + BOFF + (uint32_t)(row * BSTR + cc * 16),
                 Bm + (size_t)(kt + row) * NCOLS + (sz ? gc : 0), sz);
        }
        cpcommit();
    };

    float acc[4][8][4];
    #pragma unroll
    for (int mi = 0; mi < 4; mi++)
        #pragma unroll
        for (int n8 = 0; n8 < 8; n8++)
            #pragma unroll
            for (int q = 0; q < 4; q++) acc[mi][n8][q] = 0.f;

    issue(0, 0); issue(32, 1); issue(64, 2);

    for (int it = 0; it < 32; it++) {
        asm volatile("cp.async.wait_group 2;");
        __syncthreads();
        if (it + 3 < 32) issue((it + 3) * 32, (it + 3) & 3);
        else cpcommit();
        uint32_t base = sb + (uint32_t)(it & 3) * STGB;

        #pragma unroll
        for (int ks = 0; ks < 2; ks++) {
            int k0 = ks * 16;
            uint32_t af[4][4], bf[4][4];
            #pragma unroll
            for (int mi = 0; mi < 4; mi++) {
                int trow = wm * 64 + mi * 16 + (quad & 1) * 8 + qr;
                ldsm4(af[mi], base + (uint32_t)(trow * ASTR + (k0 + (quad >> 1) * 8) * 2));
            }
            #pragma unroll
            for (int nj = 0; nj < 4; nj++) {
                int ncol = wn * 64 + nj * 16 + (quad >> 1) * 8;
                ldsm4t(bf[nj], base + BOFF +
                       (uint32_t)((k0 + (quad & 1) * 8 + qr) * BSTR + ncol * 2));
            }
            #pragma unroll
            for (int mi = 0; mi < 4; mi++)
                #pragma unroll
                for (int n8 = 0; n8 < 8; n8++)
                    mmaH(acc[mi][n8], af[mi], bf[n8 >> 1][(n8 & 1) * 2], bf[n8 >> 1][(n8 & 1) * 2 + 1]);
        }
    }

    #pragma unroll
    for (int mi = 0; mi < 4; mi++) {
        int r = row0 + wm * 64 + mi * 16 + g;
        #pragma unroll
        for (int n8 = 0; n8 < 8; n8++) {
            int c = col0 + wn * 64 + n8 * 8 + tg * 2;
            if (c < NCOLS) {
                if (stage == 1) {
                    *(__half2*)(g_x1 + (size_t)r * NCOLS + c) =
                        __floats2half2_rn(acc[mi][n8][0], acc[mi][n8][1]);
                    *(__half2*)(g_x1 + (size_t)(r + 8) * NCOLS + c) =
                        __floats2half2_rn(acc[mi][n8][2], acc[mi][n8][3]);
                } else {
                    float2 d0 = __half22float2(*(const __half2*)(g_x0 + (size_t)r * NCOLS + c));
                    float2 d1 = __half22float2(*(const __half2*)(g_x0 + (size_t)(r + 8) * NCOLS + c));
                    *(__half2*)(g_x2 + (size_t)r * NCOLS + c) =
                        __floats2half2_rn(2.f * acc[mi][n8][0] - d0.x, 2.f * acc[mi][n8][1] - d0.y);
                    *(__half2*)(g_x2 + (size_t)(r + 8) * NCOLS + c) =
                        __floats2half2_rn(2.f * acc[mi][n8][2] - d1.x, 2.f * acc[mi][n8][3] - d1.y);
                }
            }
        }
    }
}

// ---------------- node kernels: fp16 mma, full tiles in smem, one sync ----------------
// sA: [208 rows ki][72 halves b]  (stride 144B, conflict-free ldsm)
// sW: [208 rows ki][136/72 halves o]
#define KPAD 208
#define SA_STR 72
#define SWG_STR 136
#define SWU_STR 72
#define NG_SMEM ((KPAD*SA_STR + KPAD*SWG_STR) * 2)   // 86528
#define NU_SMEM ((KPAD*SA_STR + KPAD*SWU_STR) * 2)   // 59904

__global__ __launch_bounds__(256) void k_nodegate(int t) {
    extern __shared__ __half smh[];
    __half* sA = smh;
    __half* sW = smh + KPAD * SA_STR;
    int n = blockIdx.x;
    int tid = threadIdx.x, lane = tid & 31, wid = tid >> 5;
    int wm = wid & 1, wn = wid >> 1;          // warp tile 32(m) x 32(n) over 64x128
    int g = lane >> 2, tg = lane & 3;
    int quad = lane >> 3, qr = lane & 7;
    uint32_t sa = s2u(sA), sw = s2u(sW);

    for (int ch = tid; ch < 195 * 8; ch += 256) {          // sA: xg tile
        int ki = ch >> 3, c8 = ch & 7;
        int k = ki / Cv, c = ki - k * Cv;
        const __half* plane = (k == 0) ? g_x0 : (k == 1) ? g_x1 : g_x2;
        cp16(sa + (uint32_t)(ki * SA_STR + c8 * 8) * 2,
             plane + (size_t)n * NCOLS + c * 64 + c8 * 8, 16);
    }
    const __half* Wg = g_wg + (size_t)n * JG;
    for (int ch = tid; ch < 195 * 16; ch += 256) {         // sW
        int ki = ch >> 4, c8 = ch & 15;
        cp16(sw + (uint32_t)(ki * SWG_STR + c8 * 8) * 2,
             Wg + (size_t)ki * O_G + c8 * 8, 16);
    }
    cpcommit();
    for (int i = tid; i < 13 * SA_STR; i += 256) sA[195 * SA_STR + i] = __float2half(0.f);
    for (int i = tid; i < 13 * SWG_STR; i += 256) sW[195 * SWG_STR + i] = __float2half(0.f);
    asm volatile("cp.async.wait_group 0;");
    __syncthreads();

    float acc[2][4][4];
    #pragma unroll
    for (int mi = 0; mi < 2; mi++)
        #pragma unroll
        for (int n8 = 0; n8 < 4; n8++)
            #pragma unroll
            for (int q = 0; q < 4; q++) acc[mi][n8][q] = 0.f;

    #pragma unroll
    for (int kk = 0; kk < 13; kk++) {
        int k0 = kk * 16;
        uint32_t af[2][4], bf[2][4];
        #pragma unroll
        for (int mi = 0; mi < 2; mi++) {
            int m0 = wm * 32 + mi * 16;
            ldsm4t(af[mi], sa + (uint32_t)((k0 + (quad >> 1) * 8 + qr) * SA_STR
                                           + m0 + (quad & 1) * 8) * 2);
        }
        #pragma unroll
        for (int nj = 0; nj < 2; nj++) {
            int ncol = wn * 32 + nj * 16;
            ldsm4t(bf[nj], sw + (uint32_t)((k0 + (quad & 1) * 8 + qr) * SWG_STR
                                           + ncol + (quad >> 1) * 8) * 2);
        }
        #pragma unroll
        for (int mi = 0; mi < 2; mi++)
            #pragma unroll
            for (int n8 = 0; n8 < 4; n8++)
                mmaH(acc[mi][n8], af[mi], bf[n8 >> 1][(n8 & 1) * 2], bf[n8 >> 1][(n8 & 1) * 2 + 1]);
    }

    const float* bias = g_biasg + ((size_t)t * Nv + n) * O_G;
    #pragma unroll
    for (int mi = 0; mi < 2; mi++) {
        int b0 = wm * 32 + mi * 16 + g;
        #pragma unroll
        for (int n8 = 0; n8 < 4; n8++) {
            int o0 = wn * 32 + n8 * 8 + tg * 2;
            #pragma unroll
            for (int h = 0; h < 2; h++) {
                int b = b0 + h * 8;
                size_t base = ((size_t)n * Bv + b) * Hv;
                #pragma unroll
                for (int q = 0; q < 2; q++) {
                    int oo = o0 + q;
                    float s = 1.0f / (1.0f + expf(-(acc[mi][n8][h*2+q] + bias[oo])));
                    if (oo < Hv)
                        g_x0[(size_t)n * NCOLS + (1 + oo) * 64 + b] = __float2half(s * g_h[base + oo]);
                    else
                        g_r[base + oo - Hv] = s;
                }
            }
        }
    }
}

__global__ __launch_bounds__(256) void k_nodeupd(const float* __restrict__ src, int t) {
    extern __shared__ __half smh[];
    __half* sA = smh;
    __half* sW = smh + KPAD * SA_STR;
    int n = blockIdx.x;
    int tid = threadIdx.x, lane = tid & 31, wid = tid >> 5;
    int wm = wid & 3, wn = wid >> 2;          // warp tile 16(m) x 32(n) over 64x64
    int g = lane >> 2, tg = lane & 3;
    int quad = lane >> 3, qr = lane & 7;
    uint32_t sa = s2u(sA), sw = s2u(sW);

    for (int ch = tid; ch < 195 * 8; ch += 256) {
        int ki = ch >> 3, c8 = ch & 7;
        int k = ki / Cv, c = ki - k * Cv;
        const __half* plane = (k == 0) ? g_x0 : (k == 1) ? g_x1 : g_x2;
        cp16(sa + (uint32_t)(ki * SA_STR + c8 * 8) * 2,
             plane + (size_t)n * NCOLS + c * 64 + c8 * 8, 16);
    }
    const __half* Wu = g_wu + (size_t)n * JU;
    for (int ch = tid; ch < 195 * 8; ch += 256) {
        int ki = ch >> 3, c8 = ch & 7;
        cp16(sw + (uint32_t)(ki * SWU_STR + c8 * 8) * 2,
             Wu + (size_t)ki * O_U + c8 * 8, 16);
    }
    cpcommit();
    for (int i = tid; i < 13 * SA_STR; i += 256) sA[195 * SA_STR + i] = __float2half(0.f);
    for (int i = tid; i < 13 * SWU_STR; i += 256) sW[195 * SWU_STR + i] = __float2half(0.f);
    asm volatile("cp.async.wait_group 0;");
    __syncthreads();

    float acc[4][4];
    #pragma unroll
    for (int n8 = 0; n8 < 4; n8++)
        #pragma unroll
        for (int q = 0; q < 4; q++) acc[n8][q] = 0.f;

    #pragma unroll
    for (int kk = 0; kk < 13; kk++) {
        int k0 = kk * 16;
        uint32_t af[4], bf[2][4];
        int m0 = wm * 16;
        ldsm4t(af, sa + (uint32_t)((k0 + (quad >> 1) * 8 + qr) * SA_STR
                                   + m0 + (quad & 1) * 8) * 2);
        #pragma unroll
        for (int nj = 0; nj < 2; nj++) {
            int ncol = wn * 32 + nj * 16;
            ldsm4t(bf[nj], sw + (uint32_t)((k0 + (quad & 1) * 8 + qr) * SWU_STR
                                           + ncol + (quad >> 1) * 8) * 2);
        }
        #pragma unroll
        for (int n8 = 0; n8 < 4; n8++)
            mmaH(acc[n8], af, bf[n8 >> 1][(n8 & 1) * 2], bf[n8 >> 1][(n8 & 1) * 2 + 1]);
    }

    const float* bias = g_biasu + ((size_t)t * Nv + n) * O_U;
    int b0 = wm * 16 + g;
    #pragma unroll
    for (int n8 = 0; n8 < 4; n8++) {
        int o0 = wn * 32 + n8 * 8 + tg * 2;
        #pragma unroll
        for (int h = 0; h < 2; h++) {
            int b = b0 + h * 8;
            size_t base = ((size_t)n * Bv + b) * Hv;
            #pragma unroll
            for (int q = 0; q < 2; q++) {
                int oo = o0 + q;
                float hc = tanhf(acc[n8][h*2+q] + bias[oo]);
                float rr = g_r[base + oo];
                float hnew = rr * g_h[base + oo] + (1.0f - rr) * hc;
                g_h[base + oo] = hnew;
                g_x0[(size_t)n * NCOLS + (1 + oo) * 64 + b] = __float2half(hnew);
                if (oo == 0 && t + 1 < Tv)
                    g_x0[(size_t)n * NCOLS + b] =
                        __float2half(src[(size_t)(b * Tv + t + 1) * Nv + n]);
            }
        }
    }
}

__global__ void k_zeroh() {
    int idx = blockIdx.x * blockDim.x + threadIdx.x;
    if (idx < NB * Hv) g_h[idx] = 0.f;
}

__global__ void k_final(const float* __restrict__ out_lng, const float* __restrict__ out_lnb,
                        const float* __restrict__ conv_w, const float* __restrict__ conv_b,
                        float* __restrict__ out) {
    int gw = (blockIdx.x * blockDim.x + threadIdx.x) >> 5;
    int lane = threadIdx.x & 31;
    if (gw >= NB) return;
    int n = gw / Bv, b = gw - n * Bv;
    const float* hp = g_h + (size_t)gw * Hv;
    float x0 = hp[lane], x1 = hp[lane + 32];
    float m = wredsum(x0 + x1) * (1.0f / Hv);
    float d0 = x0 - m, d1 = x1 - m;
    float vs = wredsum(d0 * d0 + d1 * d1) * (1.0f / Hv);
    float inv = rsqrtf(vs + 1e-12f);
    float y0 = d0 * inv * out_lng[lane]      + out_lnb[lane];
    float y1 = d1 * inv * out_lng[lane + 32] + out_lnb[lane + 32];
    #pragma unroll
    for (int o = 0; o < Tv; o++) {
        float p = y0 * conv_w[o*Hv + lane] + y1 * conv_w[o*Hv + lane + 32];
        p = wredsum(p);
        if (lane == 0) out[(size_t)(b*Tv + o)*Nv + n] = p + conv_b[o];
    }
}

// ================================================================================
extern "C" void kernel_launch(void* const* d_in, const int* in_sizes, int n_in,
                              void* d_out, int out_size) {
    const float* source   = (const float*)d_in[0];
    const float* node_emb = (const float*)d_in[1];
    const float* time_emb = (const float*)d_in[2];
    const float* gate_wp  = (const float*)d_in[3];
    const float* gate_bp  = (const float*)d_in[4];
    const float* gate_lng = (const float*)d_in[5];
    const float* gate_lnb = (const float*)d_in[6];
    const float* upd_wp   = (const float*)d_in[7];
    const float* upd_bp   = (const float*)d_in[8];
    const float* upd_lng  = (const float*)d_in[9];
    const float* upd_lnb  = (const float*)d_in[10];
    const float* out_lng  = (const float*)d_in[11];
    const float* out_lnb  = (const float*)d_in[12];
    const float* conv_w   = (const float*)d_in[13];
    const float* conv_b   = (const float*)d_in[14];
    float* out = (float*)d_out;

    cudaFuncSetAttribute(k_sup,      cudaFuncAttributeMaxDynamicSharedMemorySize, 1024*17*4);
    cudaFuncSetAttribute(k_hgemm,    cudaFuncAttributeMaxDynamicSharedMemorySize, 4*STGB);
    cudaFuncSetAttribute(k_nodegate, cudaFuncAttributeMaxDynamicSharedMemorySize, NG_SMEM);
    cudaFuncSetAttribute(k_nodeupd,  cudaFuncAttributeMaxDynamicSharedMemorySize, NU_SMEM);

    dim3 hGrid((NCOLS + 255)/256, Nv/128);         // 17 x 8 = 136 CTAs
    dim3 wgG((JG + 255)/256, 8);
    dim3 wgU((JU + 255)/256, 8);

    // launch index 3 = k_hgemm (the slot ncu samples)
    k_embed<<<(Tv*Nv + 255)/256, 256>>>(node_emb, time_emb, gate_lng, gate_lnb, upd_lng, upd_lnb);
    k_sup<<<dim3(Nv/16, Tv*2), 256, 1024*17*4>>>();
    k_buildX0<<<(Nv*NCOLS + 255)/256, 256>>>(source);
    k_hgemm<<<hGrid, 256, 4*STGB>>>(0, 0, 1);      // launch idx 3
    k_hgemm<<<hGrid, 256, 4*STGB>>>(0, 0, 2);
    k_wgen<<<wgG, 256>>>(gate_wp, 0, JG, 0);
    k_zeroh<<<(NB*Hv + 255)/256, 256>>>();
    k_bias<<<(Tv*Nv*O_G + 255)/256, 256>>>(gate_bp, O_G, 0);
    k_bias<<<(Tv*Nv*O_U + 255)/256, 256>>>(upd_bp,  O_U, 1);
    k_nodegate<<<Nv, 256, NG_SMEM>>>(0);
    k_wgen<<<wgU, 256>>>(upd_wp, 0, JU, 1);
    k_hgemm<<<hGrid, 256, 4*STGB>>>(1, 0, 1);
    k_hgemm<<<hGrid, 256, 4*STGB>>>(1, 0, 2);
    k_nodeupd<<<Nv, 256, NU_SMEM>>>(source, 0);

    for (int t = 1; t < Tv; t++) {
        k_wgen<<<wgG, 256>>>(gate_wp, t, JG, 0);
        k_hgemm<<<hGrid, 256, 4*STGB>>>(0, t, 1);
        k_hgemm<<<hGrid, 256, 4*STGB>>>(0, t, 2);
        k_nodegate<<<Nv, 256, NG_SMEM>>>(t);
        k_wgen<<<wgU, 256>>>(upd_wp, t, JU, 1);
        k_hgemm<<<hGrid, 256, 4*STGB>>>(1, t, 1);
        k_hgemm<<<hGrid, 256, 4*STGB>>>(1, t, 2);
        k_nodeupd<<<Nv, 256, NU_SMEM>>>(source, t);
    }

    k_final<<<(NB*32 + 255)/256, 256>>>(out_lng, out_lnb, conv_w, conv_b, out);
}

// round 17
// speedup vs baseline: 1.3835x; 1.0434x over previous
#include <cuda_runtime.h>
#include <cuda_fp16.h>
#include <math.h>
#include <stdint.h>

#define Bv 64
#define Tv 12
#define Nv 1024
#define Hv 64
#define Ev 16
#define Cv 65
#define O_G 128
#define O_U 64
#define KI 195
#define JG (KI*O_G)
#define JU (KI*O_U)
#define NB (Nv*Bv)
#define NCOLS (Bv*Cv)    // 4160; column layout: col = c*64 + b

// ---------------- static device scratch ----------------
__device__ __align__(256) float g_eg[Tv*Nv*Ev];
__device__ __align__(256) float g_eu[Tv*Nv*Ev];
__device__ __align__(256) __half g_S[(size_t)2*Tv*Nv*Nv];      // fp16 sup
__device__ __align__(256) float g_biasg[Tv*Nv*O_G];
__device__ __align__(256) float g_biasu[Tv*Nv*O_U];
__device__ __align__(256) __half g_wg[(size_t)Tv*Nv*JG];       // fp16 weights, all t (613MB)
__device__ __align__(256) __half g_wu[(size_t)Tv*Nv*JU];       // (307MB)
__device__ __align__(256) __half g_x0[(size_t)Nv*NCOLS];       // fp16 X planes (col = c*64+b)
__device__ __align__(256) __half g_x1[(size_t)Nv*NCOLS];
__device__ __align__(256) __half g_x2[(size_t)Nv*NCOLS];
__device__ __align__(256) float g_h[NB*Hv];
__device__ __align__(256) float g_r[NB*Hv];

__device__ __forceinline__ float wredsum(float v) {
    #pragma unroll
    for (int o = 16; o; o >>= 1) v += __shfl_xor_sync(0xffffffffu, v, o);
    return v;
}
__device__ __forceinline__ float wredmax(float v) {
    #pragma unroll
    for (int o = 16; o; o >>= 1) v = fmaxf(v, __shfl_xor_sync(0xffffffffu, v, o));
    return v;
}
__device__ __forceinline__ void cp16(uint32_t dst, const void* src, int sz) {
    asm volatile("cp.async.cg.shared.global [%0], [%1], 16, %2;"
                 :: "r"(dst), "l"((unsigned long long)__cvta_generic_to_global(src)), "r"(sz));
}
__device__ __forceinline__ void cpcommit() { asm volatile("cp.async.commit_group;"); }
__device__ __forceinline__ uint32_t s2u(const void* p) {
    return (uint32_t)__cvta_generic_to_shared(p);
}
__device__ __forceinline__ void mmaH(float* c, const uint32_t* a, uint32_t b0, uint32_t b1) {
    asm volatile(
        "mma.sync.aligned.m16n8k16.row.col.f32.f16.f16.f32 "
        "{%0,%1,%2,%3}, {%4,%5,%6,%7}, {%8,%9}, {%0,%1,%2,%3};"
        : "+f"(c[0]), "+f"(c[1]), "+f"(c[2]), "+f"(c[3])
        : "r"(a[0]), "r"(a[1]), "r"(a[2]), "r"(a[3]), "r"(b0), "r"(b1));
}
__device__ __forceinline__ void ldsm4(uint32_t* r, uint32_t addr) {
    asm volatile("ldmatrix.sync.aligned.m8n8.x4.shared.b16 {%0,%1,%2,%3}, [%4];"
        : "=r"(r[0]), "=r"(r[1]), "=r"(r[2]), "=r"(r[3]) : "r"(addr));
}
__device__ __forceinline__ void ldsm4t(uint32_t* r, uint32_t addr) {
    asm volatile("ldmatrix.sync.aligned.m8n8.x4.trans.shared.b16 {%0,%1,%2,%3}, [%4];"
        : "=r"(r[0]), "=r"(r[1]), "=r"(r[2]), "=r"(r[3]) : "r"(addr));
}

// ---------------- embed ----------------
__global__ void k_embed(const float* __restrict__ node_emb, const float* __restrict__ time_emb,
                        const float* __restrict__ glng, const float* __restrict__ glnb,
                        const float* __restrict__ ulng, const float* __restrict__ ulnb) {
    int idx = blockIdx.x * blockDim.x + threadIdx.x;
    if (idx >= Tv * Nv) return;
    int t = idx / Nv, n = idx - t * Nv;
    float x[Ev]; float m = 0.f;
    #pragma unroll
    for (int d = 0; d < Ev; d++) { x[d] = node_emb[n*Ev+d] + time_emb[t*Ev+d]; m += x[d]; }
    m *= (1.0f / Ev);
    float v = 0.f;
    #pragma unroll
    for (int d = 0; d < Ev; d++) { float dd = x[d] - m; v += dd * dd; }
    v *= (1.0f / Ev);
    float inv = rsqrtf(v + 1e-12f);
    #pragma unroll
    for (int d = 0; d < Ev; d++) {
        float eh = (x[d] - m) * inv;
        g_eg[(size_t)idx*Ev + d] = eh * glng[d] + glnb[d];
        g_eu[(size_t)idx*Ev + d] = eh * ulng[d] + ulnb[d];
    }
}

// ---------------- sup = softmax(e e^T), fp16 ----------------
__global__ __launch_bounds__(256) void k_sup() {
    extern __shared__ float se[];
    int bt = blockIdx.y; int t = bt >> 1; int br = bt & 1;
    const float* e = (br ? g_eu : g_eg) + (size_t)t * Nv * Ev;
    __half* S = g_S + ((size_t)(br*Tv + t) << 20);
    for (int i = threadIdx.x; i < Nv * Ev; i += 256) se[(i >> 4)*17 + (i & 15)] = e[i];
    __syncthreads();
    int wid = threadIdx.x >> 5, lane = threadIdx.x & 31;
    #pragma unroll
    for (int rr = 0; rr < 2; rr++) {
        int n = blockIdx.x * 16 + wid * 2 + rr;
        float er[Ev];
        #pragma unroll
        for (int d = 0; d < Ev; d++) er[d] = se[n*17 + d];
        float lg[32]; float mx = -1e30f;
        #pragma unroll
        for (int ii = 0; ii < 32; ii++) {
            const float* em = &se[(ii*32 + lane)*17];
            float s = 0.f;
            #pragma unroll
            for (int d = 0; d < Ev; d++) s = fmaf(er[d], em[d], s);
            lg[ii] = s; mx = fmaxf(mx, s);
        }
        mx = wredmax(mx);
        float sum = 0.f;
        #pragma unroll
        for (int ii = 0; ii < 32; ii++) { lg[ii] = expf(lg[ii] - mx); sum += lg[ii]; }
        sum = wredsum(sum);
        float inv = 1.0f / sum;
        #pragma unroll
        for (int ii = 0; ii < 32; ii++)
            S[(size_t)n * Nv + ii*32 + lane] = __float2half(lg[ii] * inv);
    }
}

// ---------------- bias ----------------
__global__ void k_bias(const float* __restrict__ bp, int O, int branch) {
    int idx = blockIdx.x * blockDim.x + threadIdx.x;
    if (idx >= Tv * Nv * O) return;
    int o = idx % O; int tn = idx / O;
    const float* e = (branch ? g_eu : g_eg) + (size_t)tn * Ev;
    float* out = branch ? g_biasu : g_biasg;
    float s = 0.f;
    #pragma unroll
    for (int d = 0; d < Ev; d++) s = fmaf(e[d], bp[d*O + o], s);
    out[idx] = s;
}

// ---------------- bulk wgen: ALL t at once -> fp16 W ----------------
// grid (jchunks, 8, Tv); 128 nodes per y-block
__global__ __launch_bounds__(256) void k_wgen(const float* __restrict__ wp, int J, int branch) {
    __shared__ float swp[Ev][256];
    __shared__ float sen[32][Ev + 1];
    int t = blockIdx.z;
    const float* e = (branch ? g_eu : g_eg) + (size_t)t * Nv * Ev;
    __half* w = (branch ? g_wu : g_wg) + (size_t)t * Nv * J;
    int tid = threadIdx.x;
    int j = blockIdx.x * 256 + tid;
    #pragma unroll
    for (int s = 0; s < Ev; s++)
        swp[s][tid] = (j < J) ? wp[(size_t)s*J + j] : 0.f;
    int nbase = blockIdx.y * 128;
    for (int cchunk = 0; cchunk < 4; cchunk++) {
        int n0 = nbase + cchunk * 32;
        __syncthreads();
        for (int i = tid; i < 32 * Ev; i += 256)
            sen[i >> 4][i & 15] = e[(size_t)(n0 + (i >> 4))*Ev + (i & 15)];
        __syncthreads();
        if (j < J) {
            for (int nn = 0; nn < 32; nn++) {
                float s = 0.f;
                #pragma unroll
                for (int d = 0; d < Ev; d++) s = fmaf(sen[nn][d], swp[d][tid], s);
                w[(size_t)(n0 + nn)*J + j] = __float2half(s);
            }
        }
    }
}

// ---------------- X0 init (col = c*64 + b) ----------------
__global__ void k_buildX0(const float* __restrict__ src) {
    int idx = blockIdx.x * blockDim.x + threadIdx.x;
    if (idx >= Nv * NCOLS) return;
    int col = idx % NCOLS; int n = idx / NCOLS;
    int cc = col >> 6, b = col & 63;
    float v = 0.f;
    if (cc == 0) v = src[(size_t)(b*Tv)*Nv + n];
    g_x0[idx] = __float2half(v);
}

// ---------------- fp16 GEMM: CTA 128x256, 256 thr, K-tile 32, 4-stage ----------------
#define ASTR 80
#define BSTR 528
#define BOFF 10240
#define STGB (BOFF + 32*BSTR)      // 27136
__global__ __launch_bounds__(256) void k_hgemm(int branch, int t, int stage) {
    extern __shared__ uint8_t smem[];
    const __half* A = g_S + ((size_t)(branch*Tv + t) << 20);
    const __half* Bm = (stage == 1) ? g_x0 : g_x1;

    int tid = threadIdx.x, lane = tid & 31, wid = tid >> 5;
    int wm = wid & 1, wn = wid >> 1;
    int row0 = blockIdx.y * 128, col0 = blockIdx.x * 256;
    int g = lane >> 2, tg = lane & 3;
    int quad = lane >> 3, qr = lane & 7;
    uint32_t sb = s2u(smem);

    auto issue = [&](int kt, int s) {
        uint32_t base = sb + (uint32_t)s * STGB;
        #pragma unroll
        for (int q = 0; q < 2; q++) {
            int id = tid + q * 256;
            int row = id >> 2, kc = id & 3;
            cp16(base + (uint32_t)(row * ASTR + kc * 16),
                 A + (size_t)(row0 + row) * Nv + kt + kc * 8, 16);
        }
        #pragma unroll
        for (int q = 0; q < 4; q++) {
            int id = tid + q * 256;
            int row = id >> 5, cc = id & 31;
            int gc = col0 + cc * 8;
            int sz = (gc < NCOLS) ? 16 : 0;
            cp16(base + BOFF + (uint32_t)(row * BSTR + cc * 16),
                 Bm + (size_t)(kt + row) * NCOLS + (sz ? gc : 0), sz);
        }
        cpcommit();
    };

    float acc[4][8][4];
    #pragma unroll
    for (int mi = 0; mi < 4; mi++)
        #pragma unroll
        for (int n8 = 0; n8 < 8; n8++)
            #pragma unroll
            for (int q = 0; q < 4; q++) acc[mi][n8][q] = 0.f;

    issue(0, 0); issue(32, 1); issue(64, 2);

    for (int it = 0; it < 32; it++) {
        asm volatile("cp.async.wait_group 2;");
        __syncthreads();
        if (it + 3 < 32) issue((it + 3) * 32, (it + 3) & 3);
        else cpcommit();
        uint32_t base = sb + (uint32_t)(it & 3) * STGB;

        #pragma unroll
        for (int ks = 0; ks < 2; ks++) {
            int k0 = ks * 16;
            uint32_t af[4][4], bf[4][4];
            #pragma unroll
            for (int mi = 0; mi < 4; mi++) {
                int trow = wm * 64 + mi * 16 + (quad & 1) * 8 + qr;
                ldsm4(af[mi], base + (uint32_t)(trow * ASTR + (k0 + (quad >> 1) * 8) * 2));
            }
            #pragma unroll
            for (int nj = 0; nj < 4; nj++) {
                int ncol = wn * 64 + nj * 16 + (quad >> 1) * 8;
                ldsm4t(bf[nj], base + BOFF +
                       (uint32_t)((k0 + (quad & 1) * 8 + qr) * BSTR + ncol * 2));
            }
            #pragma unroll
            for (int mi = 0; mi < 4; mi++)
                #pragma unroll
                for (int n8 = 0; n8 < 8; n8++)
                    mmaH(acc[mi][n8], af[mi], bf[n8 >> 1][(n8 & 1) * 2], bf[n8 >> 1][(n8 & 1) * 2 + 1]);
        }
    }

    #pragma unroll
    for (int mi = 0; mi < 4; mi++) {
        int r = row0 + wm * 64 + mi * 16 + g;
        #pragma unroll
        for (int n8 = 0; n8 < 8; n8++) {
            int c = col0 + wn * 64 + n8 * 8 + tg * 2;
            if (c < NCOLS) {
                if (stage == 1) {
                    *(__half2*)(g_x1 + (size_t)r * NCOLS + c) =
                        __floats2half2_rn(acc[mi][n8][0], acc[mi][n8][1]);
                    *(__half2*)(g_x1 + (size_t)(r + 8) * NCOLS + c) =
                        __floats2half2_rn(acc[mi][n8][2], acc[mi][n8][3]);
                } else {
                    float2 d0 = __half22float2(*(const __half2*)(g_x0 + (size_t)r * NCOLS + c));
                    float2 d1 = __half22float2(*(const __half2*)(g_x0 + (size_t)(r + 8) * NCOLS + c));
                    *(__half2*)(g_x2 + (size_t)r * NCOLS + c) =
                        __floats2half2_rn(2.f * acc[mi][n8][0] - d0.x, 2.f * acc[mi][n8][1] - d0.y);
                    *(__half2*)(g_x2 + (size_t)(r + 8) * NCOLS + c) =
                        __floats2half2_rn(2.f * acc[mi][n8][2] - d1.x, 2.f * acc[mi][n8][3] - d1.y);
                }
            }
        }
    }
}

// ---------------- node kernels: fp16 mma, full tiles in smem, one sync ----------------
#define KPAD 208
#define SA_STR 72
#define SWG_STR 136
#define SWU_STR 72
#define NG_SMEM ((KPAD*SA_STR + KPAD*SWG_STR) * 2)   // 86528
#define NU_SMEM ((KPAD*SA_STR + KPAD*SWU_STR) * 2)   // 59904

__global__ __launch_bounds__(256) void k_nodegate(int t) {
    extern __shared__ __half smh[];
    __half* sA = smh;
    __half* sW = smh + KPAD * SA_STR;
    int n = blockIdx.x;
    int tid = threadIdx.x, lane = tid & 31, wid = tid >> 5;
    int wm = wid & 1, wn = wid >> 1;          // warp tile 32(m) x 32(n) over 64x128
    int g = lane >> 2, tg = lane & 3;
    int quad = lane >> 3, qr = lane & 7;
    uint32_t sa = s2u(sA), sw = s2u(sW);

    for (int ch = tid; ch < 195 * 8; ch += 256) {          // sA: xg tile
        int ki = ch >> 3, c8 = ch & 7;
        int k = ki / Cv, c = ki - k * Cv;
        const __half* plane = (k == 0) ? g_x0 : (k == 1) ? g_x1 : g_x2;
        cp16(sa + (uint32_t)(ki * SA_STR + c8 * 8) * 2,
             plane + (size_t)n * NCOLS + c * 64 + c8 * 8, 16);
    }
    const __half* Wg = g_wg + ((size_t)t * Nv + n) * JG;
    for (int ch = tid; ch < 195 * 16; ch += 256) {         // sW
        int ki = ch >> 4, c8 = ch & 15;
        cp16(sw + (uint32_t)(ki * SWG_STR + c8 * 8) * 2,
             Wg + (size_t)ki * O_G + c8 * 8, 16);
    }
    cpcommit();
    for (int i = tid; i < 13 * SA_STR; i += 256) sA[195 * SA_STR + i] = __float2half(0.f);
    for (int i = tid; i < 13 * SWG_STR; i += 256) sW[195 * SWG_STR + i] = __float2half(0.f);
    asm volatile("cp.async.wait_group 0;");
    __syncthreads();

    float acc[2][4][4];
    #pragma unroll
    for (int mi = 0; mi < 2; mi++)
        #pragma unroll
        for (int n8 = 0; n8 < 4; n8++)
            #pragma unroll
            for (int q = 0; q < 4; q++) acc[mi][n8][q] = 0.f;

    #pragma unroll
    for (int kk = 0; kk < 13; kk++) {
        int k0 = kk * 16;
        uint32_t af[2][4], bf[2][4];
        #pragma unroll
        for (int mi = 0; mi < 2; mi++) {
            int m0 = wm * 32 + mi * 16;
            ldsm4t(af[mi], sa + (uint32_t)((k0 + (quad >> 1) * 8 + qr) * SA_STR
                                           + m0 + (quad & 1) * 8) * 2);
        }
        #pragma unroll
        for (int nj = 0; nj < 2; nj++) {
            int ncol = wn * 32 + nj * 16;
            ldsm4t(bf[nj], sw + (uint32_t)((k0 + (quad & 1) * 8 + qr) * SWG_STR
                                           + ncol + (quad >> 1) * 8) * 2);
        }
        #pragma unroll
        for (int mi = 0; mi < 2; mi++)
            #pragma unroll
            for (int n8 = 0; n8 < 4; n8++)
                mmaH(acc[mi][n8], af[mi], bf[n8 >> 1][(n8 & 1) * 2], bf[n8 >> 1][(n8 & 1) * 2 + 1]);
    }

    const float* bias = g_biasg + ((size_t)t * Nv + n) * O_G;
    #pragma unroll
    for (int mi = 0; mi < 2; mi++) {
        int b0 = wm * 32 + mi * 16 + g;
        #pragma unroll
        for (int n8 = 0; n8 < 4; n8++) {
            int o0 = wn * 32 + n8 * 8 + tg * 2;
            #pragma unroll
            for (int h = 0; h < 2; h++) {
                int b = b0 + h * 8;
                size_t base = ((size_t)n * Bv + b) * Hv;
                #pragma unroll
                for (int q = 0; q < 2; q++) {
                    int oo = o0 + q;
                    float s = 1.0f / (1.0f + expf(-(acc[mi][n8][h*2+q] + bias[oo])));
                    if (oo < Hv)
                        g_x0[(size_t)n * NCOLS + (1 + oo) * 64 + b] = __float2half(s * g_h[base + oo]);
                    else
                        g_r[base + oo - Hv] = s;
                }
            }
        }
    }
}

__global__ __launch_bounds__(256) void k_nodeupd(const float* __restrict__ src, int t) {
    extern __shared__ __half smh[];
    __half* sA = smh;
    __half* sW = smh + KPAD * SA_STR;
    int n = blockIdx.x;
    int tid = threadIdx.x, lane = tid & 31, wid = tid >> 5;
    int wm = wid & 3, wn = wid >> 2;          // warp tile 16(m) x 32(n) over 64x64
    int g = lane >> 2, tg = lane & 3;
    int quad = lane >> 3, qr = lane & 7;
    uint32_t sa = s2u(sA), sw = s2u(sW);

    for (int ch = tid; ch < 195 * 8; ch += 256) {
        int ki = ch >> 3, c8 = ch & 7;
        int k = ki / Cv, c = ki - k * Cv;
        const __half* plane = (k == 0) ? g_x0 : (k == 1) ? g_x1 : g_x2;
        cp16(sa + (uint32_t)(ki * SA_STR + c8 * 8) * 2,
             plane + (size_t)n * NCOLS + c * 64 + c8 * 8, 16);
    }
    const __half* Wu = g_wu + ((size_t)t * Nv + n) * JU;
    for (int ch = tid; ch < 195 * 8; ch += 256) {
        int ki = ch >> 3, c8 = ch & 7;
        cp16(sw + (uint32_t)(ki * SWU_STR + c8 * 8) * 2,
             Wu + (size_t)ki * O_U + c8 * 8, 16);
    }
    cpcommit();
    for (int i = tid; i < 13 * SA_STR; i += 256) sA[195 * SA_STR + i] = __float2half(0.f);
    for (int i = tid; i < 13 * SWU_STR; i += 256) sW[195 * SWU_STR + i] = __float2half(0.f);
    asm volatile("cp.async.wait_group 0;");
    __syncthreads();

    float acc[4][4];
    #pragma unroll
    for (int n8 = 0; n8 < 4; n8++)
        #pragma unroll
        for (int q = 0; q < 4; q++) acc[n8][q] = 0.f;

    #pragma unroll
    for (int kk = 0; kk < 13; kk++) {
        int k0 = kk * 16;
        uint32_t af[4], bf[2][4];
        int m0 = wm * 16;
        ldsm4t(af, sa + (uint32_t)((k0 + (quad >> 1) * 8 + qr) * SA_STR
                                   + m0 + (quad & 1) * 8) * 2);
        #pragma unroll
        for (int nj = 0; nj < 2; nj++) {
            int ncol = wn * 32 + nj * 16;
            ldsm4t(bf[nj], sw + (uint32_t)((k0 + (quad & 1) * 8 + qr) * SWU_STR
                                           + ncol + (quad >> 1) * 8) * 2);
        }
        #pragma unroll
        for (int n8 = 0; n8 < 4; n8++)
            mmaH(acc[n8], af, bf[n8 >> 1][(n8 & 1) * 2], bf[n8 >> 1][(n8 & 1) * 2 + 1]);
    }

    const float* bias = g_biasu + ((size_t)t * Nv + n) * O_U;
    int b0 = wm * 16 + g;
    #pragma unroll
    for (int n8 = 0; n8 < 4; n8++) {
        int o0 = wn * 32 + n8 * 8 + tg * 2;
        #pragma unroll
        for (int h = 0; h < 2; h++) {
            int b = b0 + h * 8;
            size_t base = ((size_t)n * Bv + b) * Hv;
            #pragma unroll
            for (int q = 0; q < 2; q++) {
                int oo = o0 + q;
                float hc = tanhf(acc[n8][h*2+q] + bias[oo]);
                float rr = g_r[base + oo];
                float hnew = rr * g_h[base + oo] + (1.0f - rr) * hc;
                g_h[base + oo] = hnew;
                g_x0[(size_t)n * NCOLS + (1 + oo) * 64 + b] = __float2half(hnew);
                if (oo == 0 && t + 1 < Tv)
                    g_x0[(size_t)n * NCOLS + b] =
                        __float2half(src[(size_t)(b * Tv + t + 1) * Nv + n]);
            }
        }
    }
}

__global__ void k_zeroh() {
    int idx = blockIdx.x * blockDim.x + threadIdx.x;
    if (idx < NB * Hv) g_h[idx] = 0.f;
}

__global__ void k_final(const float* __restrict__ out_lng, const float* __restrict__ out_lnb,
                        const float* __restrict__ conv_w, const float* __restrict__ conv_b,
                        float* __restrict__ out) {
    int gw = (blockIdx.x * blockDim.x + threadIdx.x) >> 5;
    int lane = threadIdx.x & 31;
    if (gw >= NB) return;
    int n = gw / Bv, b = gw - n * Bv;
    const float* hp = g_h + (size_t)gw * Hv;
    float x0 = hp[lane], x1 = hp[lane + 32];
    float m = wredsum(x0 + x1) * (1.0f / Hv);
    float d0 = x0 - m, d1 = x1 - m;
    float vs = wredsum(d0 * d0 + d1 * d1) * (1.0f / Hv);
    float inv = rsqrtf(vs + 1e-12f);
    float y0 = d0 * inv * out_lng[lane]      + out_lnb[lane];
    float y1 = d1 * inv * out_lng[lane + 32] + out_lnb[lane + 32];
    #pragma unroll
    for (int o = 0; o < Tv; o++) {
        float p = y0 * conv_w[o*Hv + lane] + y1 * conv_w[o*Hv + lane + 32];
        p = wredsum(p);
        if (lane == 0) out[(size_t)(b*Tv + o)*Nv + n] = p + conv_b[o];
    }
}

// ================================================================================
extern "C" void kernel_launch(void* const* d_in, const int* in_sizes, int n_in,
                              void* d_out, int out_size) {
    const float* source   = (const float*)d_in[0];
    const float* node_emb = (const float*)d_in[1];
    const float* time_emb = (const float*)d_in[2];
    const float* gate_wp  = (const float*)d_in[3];
    const float* gate_bp  = (const float*)d_in[4];
    const float* gate_lng = (const float*)d_in[5];
    const float* gate_lnb = (const float*)d_in[6];
    const float* upd_wp   = (const float*)d_in[7];
    const float* upd_bp   = (const float*)d_in[8];
    const float* upd_lng  = (const float*)d_in[9];
    const float* upd_lnb  = (const float*)d_in[10];
    const float* out_lng  = (const float*)d_in[11];
    const float* out_lnb  = (const float*)d_in[12];
    const float* conv_w   = (const float*)d_in[13];
    const float* conv_b   = (const float*)d_in[14];
    float* out = (float*)d_out;

    cudaFuncSetAttribute(k_sup,      cudaFuncAttributeMaxDynamicSharedMemorySize, 1024*17*4);
    cudaFuncSetAttribute(k_hgemm,    cudaFuncAttributeMaxDynamicSharedMemorySize, 4*STGB);
    cudaFuncSetAttribute(k_nodegate, cudaFuncAttributeMaxDynamicSharedMemorySize, NG_SMEM);
    cudaFuncSetAttribute(k_nodeupd,  cudaFuncAttributeMaxDynamicSharedMemorySize, NU_SMEM);

    dim3 hGrid((NCOLS + 255)/256, Nv/128);         // 17 x 8 = 136 CTAs
    dim3 wgG((JG + 255)/256, 8, Tv);               // bulk: all t
    dim3 wgU((JU + 255)/256, 8, Tv);

    // prologue; launch idx 3 = bulk k_wgen (profiled slot)
    k_embed<<<(Tv*Nv + 255)/256, 256>>>(node_emb, time_emb, gate_lng, gate_lnb, upd_lng, upd_lnb);
    k_sup<<<dim3(Nv/16, Tv*2), 256, 1024*17*4>>>();
    k_buildX0<<<(Nv*NCOLS + 255)/256, 256>>>(source);
    k_wgen<<<wgG, 256>>>(gate_wp, JG, 0);          // launch idx 3
    k_wgen<<<wgU, 256>>>(upd_wp, JU, 1);
    k_zeroh<<<(NB*Hv + 255)/256, 256>>>();
    k_bias<<<(Tv*Nv*O_G + 255)/256, 256>>>(gate_bp, O_G, 0);
    k_bias<<<(Tv*Nv*O_U + 255)/256, 256>>>(upd_bp,  O_U, 1);

    for (int t = 0; t < Tv; t++) {
        k_hgemm<<<hGrid, 256, 4*STGB>>>(0, t, 1);
        k_hgemm<<<hGrid, 256, 4*STGB>>>(0, t, 2);
        k_nodegate<<<Nv, 256, NG_SMEM>>>(t);
        k_hgemm<<<hGrid, 256, 4*STGB>>>(1, t, 1);
        k_hgemm<<<hGrid, 256, 4*STGB>>>(1, t, 2);
        k_nodeupd<<<Nv, 256, NU_SMEM>>>(source, t);
    }

    k_final<<<(NB*32 + 255)/256, 256>>>(out_lng, out_lnb, conv_w, conv_b, out);
}